// round 4
// baseline (speedup 1.0000x reference)
#include <cuda_runtime.h>
#include <stdint.h>

// Problem constants
#define NT    256      // threads per CTA
#define NB    4        // b-values per CTA (1 per 64-thread group)
#define DIM   40
#define NPAIR 820      // DIM*(DIM+1)/2 unique symmetric pairs
#define NROWS 860      // pairs + 40 U1 rows
#define TS    16       // table row stride (floats)

// Packed coefficient table:
//  rows [0,820): per pair (i<=j): 13 symmetric-folded U2 coeffs (off-diag doubled), 3 pad(0)
//  rows [820,860): per i: 13 U1 coeffs, 3 pad(0)
//  pair order matches the compile-time double loop: p = i*DIM - i*(i-1)/2 + (j-i)
__device__ float g_table[NROWS * TS];

__global__ void prep_kernel(const float* __restrict__ U2_0,
                            const float* __restrict__ U1_0,
                            const float* __restrict__ U2_1,
                            const float* __restrict__ U1_1,
                            const float* __restrict__ U2_2,
                            const float* __restrict__ U1_2) {
    int idx = blockIdx.x * blockDim.x + threadIdx.x;
    if (idx >= NROWS) return;
    float row[TS];
#pragma unroll
    for (int k = 0; k < TS; k++) row[k] = 0.0f;

    if (idx < NPAIR) {
        // invert p -> (i, j) for row-major triangular order (i outer, j from i)
        int p = idx;
        int i = 0;
        int rem = p;
        while (rem >= DIM - i) { rem -= DIM - i; i++; }
        int j = i + rem;
        const float* U2b[3] = {U2_0, U2_1, U2_2};
#pragma unroll
        for (int m = 0; m < 13; m++) {
            int l  = (m == 0) ? 0 : ((m < 4) ? 1 : 2);
            int mm = (m == 0) ? 0 : ((m < 4) ? (m - 1) : (m - 4));
            const float* U = U2b[l];
            float v = U[(mm * DIM + i) * DIM + j];
            if (i != j) v += U[(mm * DIM + j) * DIM + i];
            row[m] = v;
        }
    } else {
        int i = idx - NPAIR;
        const float* U1b[3] = {U1_0, U1_1, U1_2};
#pragma unroll
        for (int m = 0; m < 13; m++) {
            int l  = (m == 0) ? 0 : ((m < 4) ? 1 : 2);
            int mm = (m == 0) ? 0 : ((m < 4) ? (m - 1) : (m - 4));
            row[m] = U1b[l][mm * DIM + i];
        }
    }
#pragma unroll
    for (int k = 0; k < TS; k++) g_table[idx * TS + k] = row[k];
}

// ---- packed f32x2 helpers (FFMA2 is only reachable via PTX) ----
__device__ __forceinline__ void fma2(unsigned long long& acc,
                                     unsigned long long u,
                                     unsigned long long y) {
    asm("fma.rn.f32x2 %0, %1, %2, %0;" : "+l"(acc) : "l"(u), "l"(y));
}
__device__ __forceinline__ unsigned long long dup2(float y) {
    unsigned long long r;
    asm("mov.b64 %0, {%1, %1};" : "=l"(r) : "f"(y));
    return r;
}
__device__ __forceinline__ float2 unpk2(unsigned long long v) {
    float2 r;
    asm("mov.b64 {%0, %1}, %2;" : "=f"(r.x), "=f"(r.y) : "l"(v));
    return r;
}

// one table row: 13 coeffs packed as 6.5 f32x2
__device__ __forceinline__ void row_fma(const char* tb, int off,
                                        unsigned long long yy,
                                        unsigned long long* acc) {
    ulonglong2 q0 = *(const ulonglong2*)(tb + off);
    ulonglong2 q1 = *(const ulonglong2*)(tb + off + 16);
    ulonglong2 q2 = *(const ulonglong2*)(tb + off + 32);
    unsigned long long q3 = *(const unsigned long long*)(tb + off + 48);
    fma2(acc[0], q0.x, yy);
    fma2(acc[1], q0.y, yy);
    fma2(acc[2], q1.x, yy);
    fma2(acc[3], q1.y, yy);
    fma2(acc[4], q2.x, yy);
    fma2(acc[5], q2.y, yy);
    fma2(acc[6], q3,   yy);   // (m12, 0) — high half accumulates 0*y
}

// SMEM layout (floats):
//   [0,     13760)  coeff table (55 KB); first 12288 reused for Wlin in epilogue
//   [13760, 17856)  basis[4 b][64 c][16 m] (16 KB)
#define SMEM_FLOATS 17856
#define SMEM_BYTES  (SMEM_FLOATS * 4)

__global__ __launch_bounds__(NT, 2)
void main_kernel(const float* __restrict__ f0,  const float* __restrict__ f1,
                 const float* __restrict__ f2,  const float* __restrict__ f3,
                 const float* __restrict__ attrs,
                 const float* __restrict__ W1_0, const float* __restrict__ W2_0,
                 const float* __restrict__ Wl0,  const float* __restrict__ sc0,
                 const float* __restrict__ W1_1, const float* __restrict__ W2_1,
                 const float* __restrict__ Wl1,  const float* __restrict__ sc1,
                 const float* __restrict__ W1_2, const float* __restrict__ W2_2,
                 const float* __restrict__ Wl2,  const float* __restrict__ sc2,
                 float* __restrict__ out, int B) {
    extern __shared__ float S[];
    float* tabS = S;            // 13760 floats
    float* basS = S + 13760;    // 4096 floats

    const int tid = threadIdx.x;
    const int bl  = tid >> 6;
    const int c   = tid & 63;
    int b = blockIdx.x * NB + bl;
    const bool active = (b < B);
    if (b >= B) b = B - 1;
    const int bci = b * 64 + c;

    // cooperative copy of the packed table into smem
    {
        const float4* gt4 = (const float4*)g_table;
        float4* tp4 = (float4*)tabS;
#pragma unroll
        for (int k = 0; k < NROWS * TS / 4 / NT + 1; k++) {
            int idx = k * NT + tid;
            if (idx < NROWS * TS / 4) tp4[idx] = gt4[idx];
        }
    }

    // x[40] lives in REGISTERS (pair loop is fully unrolled, indices compile-time)
    float x[DIM];
    x[0] = f0[bci];
#pragma unroll
    for (int k = 0; k < 3; k++)  x[1 + k]  = f1[bci * 3 + k];
#pragma unroll
    for (int k = 0; k < 9; k++)  x[4 + k]  = f2[bci * 9 + k];
#pragma unroll
    for (int k = 0; k < 27; k++) x[13 + k] = f3[bci * 27 + k];

    // element-aware channel weights
    float w1[3] = {0.f, 0.f, 0.f}, w2[3] = {0.f, 0.f, 0.f};
#pragma unroll
    for (int e = 0; e < 10; e++) {
        float a = __ldg(&attrs[b * 10 + e]);
        w1[0] += a * __ldg(&W1_0[e * 64 + c]);
        w2[0] += a * __ldg(&W2_0[e * 64 + c]);
        w1[1] += a * __ldg(&W1_1[e * 64 + c]);
        w2[1] += a * __ldg(&W2_1[e * 64 + c]);
        w1[2] += a * __ldg(&W1_2[e * 64 + c]);
        w2[2] += a * __ldg(&W2_2[e * 64 + c]);
    }
    __syncthreads();

    const char* tb = (const char*)tabS;
    const int LSEL[14] = {0, 1, 1, 1, 2, 2, 2, 2, 2, 2, 2, 2, 2, 0};

    // ---- phase A: a2[m] = sum_{i<=j} u[p][m] * x_i * x_j  (fully unrolled) ----
    unsigned long long acc[7];
#pragma unroll
    for (int k = 0; k < 7; k++) acc[k] = 0ull;
    {
        int p = 0;
#pragma unroll
        for (int i = 0; i < DIM; i++) {
#pragma unroll
            for (int j = i; j < DIM; j++) {
                unsigned long long yy = dup2(x[i] * x[j]);
                row_fma(tb, p * 64, yy, acc);
                p++;
            }
        }
    }
    // fold a2 * w2 into basis smem
    {
        float* bs = basS + tid * 16;
#pragma unroll
        for (int k = 0; k < 7; k++) {
            float2 v = unpk2(acc[k]);
            int m0 = 2 * k, m1 = 2 * k + 1;
            bs[m0] = v.x * w2[LSEL[m0]];
            if (m1 < 13) bs[m1] = v.y * w2[LSEL[m1]];
        }
    }

    // ---- phase B: a1[m] = U1[m,:] . x ----
#pragma unroll
    for (int k = 0; k < 7; k++) acc[k] = 0ull;
#pragma unroll
    for (int i = 0; i < DIM; i++) {
        unsigned long long yy = dup2(x[i]);
        row_fma(tb, (NPAIR + i) * 64, yy, acc);
    }
    {
        float* bs = basS + tid * 16;
#pragma unroll
        for (int k = 0; k < 7; k++) {
            float2 v = unpk2(acc[k]);
            int m0 = 2 * k, m1 = 2 * k + 1;
            bs[m0] += v.x * w1[LSEL[m0]];
            if (m1 < 13) bs[m1] += v.y * w1[LSEL[m1]];
        }
    }
    __syncthreads();

    // ---- reuse table region for Wlin cache: wlS[l*4096 + cc*64 + o] ----
    float* wlS = S;
    {
        const float4* a0p = (const float4*)Wl0;
        const float4* a1p = (const float4*)Wl1;
        const float4* a2p = (const float4*)Wl2;
        float4* w4 = (float4*)wlS;
#pragma unroll
        for (int k = 0; k < 4; k++) {
            int idx = k * NT + tid;
            w4[idx]        = a0p[idx];
            w4[1024 + idx] = a1p[idx];
            w4[2048 + idx] = a2p[idx];
        }
    }
    __syncthreads();

    // ---- self-interaction: r[m] = sum_cc basis[b][cc][m] * Wlin_l[cc][c] ----
    float r[13];
#pragma unroll
    for (int m = 0; m < 13; m++) r[m] = 0.0f;
    const float* bb = basS + bl * 64 * 16;
#pragma unroll 4
    for (int cc = 0; cc < 64; cc++) {
        const float* br = bb + cc * 16;
        float4 b0 = *(const float4*)(br);
        float4 b1 = *(const float4*)(br + 4);
        float4 b2 = *(const float4*)(br + 8);
        float b12 = br[12];
        float wv0 = wlS[cc * 64 + c];
        float wv1 = wlS[4096 + cc * 64 + c];
        float wv2 = wlS[8192 + cc * 64 + c];
        r[0]  += b0.x * wv0;
        r[1]  += b0.y * wv1;
        r[2]  += b0.z * wv1;
        r[3]  += b0.w * wv1;
        r[4]  += b1.x * wv2;
        r[5]  += b1.y * wv2;
        r[6]  += b1.z * wv2;
        r[7]  += b1.w * wv2;
        r[8]  += b2.x * wv2;
        r[9]  += b2.y * wv2;
        r[10] += b2.z * wv2;
        r[11] += b2.w * wv2;
        r[12] += b12  * wv2;
    }

    if (!active) return;

    // outputs: concat [out0 (B,C)] [out1 (B,C,3)] [out2 (B,C,9)]
    float* o0 = out;
    float* o1 = out + (size_t)B * 64;
    float* o2 = out + (size_t)B * 64 * 4;
    const int bo = b * 64 + c;
    o0[bo] = r[0] + __ldg(&sc0[bo]);
#pragma unroll
    for (int k = 0; k < 3; k++) o1[bo * 3 + k] = r[1 + k] + __ldg(&sc1[bo * 3 + k]);
#pragma unroll
    for (int k = 0; k < 9; k++) o2[bo * 9 + k] = r[4 + k] + __ldg(&sc2[bo * 9 + k]);
}

extern "C" void kernel_launch(void* const* d_in, const int* in_sizes, int n_in,
                              void* d_out, int out_size) {
    const float* f0    = (const float*)d_in[0];
    const float* f1    = (const float*)d_in[1];
    const float* f2    = (const float*)d_in[2];
    const float* f3    = (const float*)d_in[3];
    const float* attrs = (const float*)d_in[4];
    const float* U2_0  = (const float*)d_in[5];
    const float* U1_0  = (const float*)d_in[6];
    const float* W1_0  = (const float*)d_in[7];
    const float* W2_0  = (const float*)d_in[8];
    const float* Wl0   = (const float*)d_in[9];
    const float* sc0   = (const float*)d_in[10];
    const float* U2_1  = (const float*)d_in[11];
    const float* U1_1  = (const float*)d_in[12];
    const float* W1_1  = (const float*)d_in[13];
    const float* W2_1  = (const float*)d_in[14];
    const float* Wl1   = (const float*)d_in[15];
    const float* sc1   = (const float*)d_in[16];
    const float* U2_2  = (const float*)d_in[17];
    const float* U1_2  = (const float*)d_in[18];
    const float* W1_2  = (const float*)d_in[19];
    const float* W2_2  = (const float*)d_in[20];
    const float* Wl2   = (const float*)d_in[21];
    const float* sc2   = (const float*)d_in[22];

    const int B = in_sizes[0] / 64;

    cudaFuncSetAttribute(main_kernel,
                         cudaFuncAttributeMaxDynamicSharedMemorySize, SMEM_BYTES);

    prep_kernel<<<(NROWS + 255) / 256, 256>>>(U2_0, U1_0, U2_1, U1_1, U2_2, U1_2);

    const int grid = (B + NB - 1) / NB;
    main_kernel<<<grid, NT, SMEM_BYTES>>>(f0, f1, f2, f3, attrs,
                                          W1_0, W2_0, Wl0, sc0,
                                          W1_1, W2_1, Wl1, sc1,
                                          W1_2, W2_2, Wl2, sc2,
                                          (float*)d_out, B);
}

// round 5
// speedup vs baseline: 2.0100x; 2.0100x over previous
#include <cuda_runtime.h>
#include <stdint.h>

// Problem constants
#define NT    512      // threads per CTA (8 groups x 64 channels)
#define NBSUB 2        // b-values per thread
#define NB    16       // b-values per CTA
#define DIM   40
#define NPAIR 820      // DIM*(DIM+1)/2 unique symmetric pairs
#define NROWS 860      // pairs + 40 U1 rows
#define TS    16       // table row stride (floats)
#define XROWB 4096     // x_s row stride in bytes (512 threads * 8B)

// Packed coefficient table:
//  rows [0,820): per pair (i<=j): 13 symmetric-folded U2 coeffs (off-diag doubled),
//                pad(0), then bit-cast byte offsets i*4096, j*4096
//  rows [820,860): per i: 13 U1 coeffs, pad, offset i*4096, 0
__device__ float g_table[NROWS * TS];

__global__ void prep_kernel(const float* __restrict__ U2_0,
                            const float* __restrict__ U1_0,
                            const float* __restrict__ U2_1,
                            const float* __restrict__ U1_1,
                            const float* __restrict__ U2_2,
                            const float* __restrict__ U1_2) {
    int idx = blockIdx.x * blockDim.x + threadIdx.x;
    if (idx >= NROWS) return;
    float row[TS];
#pragma unroll
    for (int k = 0; k < TS; k++) row[k] = 0.0f;

    if (idx < NPAIR) {
        int p = idx;
        int j = 0;
        while ((j + 1) * (j + 2) / 2 <= p) j++;
        int i = p - j * (j + 1) / 2;   // i <= j
        const float* U2b[3] = {U2_0, U2_1, U2_2};
#pragma unroll
        for (int m = 0; m < 13; m++) {
            int l  = (m == 0) ? 0 : ((m < 4) ? 1 : 2);
            int mm = (m == 0) ? 0 : ((m < 4) ? (m - 1) : (m - 4));
            const float* U = U2b[l];
            float v = U[(mm * DIM + i) * DIM + j];
            if (i != j) v += U[(mm * DIM + j) * DIM + i];
            row[m] = v;
        }
        row[13] = 0.0f;
        row[14] = __int_as_float(i * XROWB);
        row[15] = __int_as_float(j * XROWB);
    } else {
        int i = idx - NPAIR;
        const float* U1b[3] = {U1_0, U1_1, U1_2};
#pragma unroll
        for (int m = 0; m < 13; m++) {
            int l  = (m == 0) ? 0 : ((m < 4) ? 1 : 2);
            int mm = (m == 0) ? 0 : ((m < 4) ? (m - 1) : (m - 4));
            row[m] = U1b[l][mm * DIM + i];
        }
        row[13] = 0.0f;
        row[14] = __int_as_float(i * XROWB);
        row[15] = __int_as_float(0);
    }
#pragma unroll
    for (int k = 0; k < TS; k++) g_table[idx * TS + k] = row[k];
}

// ---- packed f32x2 helpers ----
__device__ __forceinline__ void fma2(unsigned long long& acc,
                                     unsigned long long u,
                                     unsigned long long y) {
    asm("fma.rn.f32x2 %0, %1, %2, %0;" : "+l"(acc) : "l"(u), "l"(y));
}
__device__ __forceinline__ unsigned long long dup2(float y) {
    unsigned long long r;
    asm("mov.b64 %0, {%1, %1};" : "=l"(r) : "f"(y));
    return r;
}
__device__ __forceinline__ float2 unpk2(unsigned long long v) {
    float2 r;
    asm("mov.b64 {%0, %1}, %2;" : "=f"(r.x), "=f"(r.y) : "l"(v));
    return r;
}

// SMEM layout (floats):
//   [0,     13760)  coeff table (55 KB)
//   [13760, 54720)  xS: x[40][512 threads][2 b]  (160 KB)
//                   reused after phases: basis[16][64][20] (80 KB) + Wlin (48 KB)
#define SMEM_FLOATS 54720
#define SMEM_BYTES  (SMEM_FLOATS * 4)
#define BSTRIDE 20     // basis row stride in floats (float4-aligned, 4-way conflicts)

__global__ __launch_bounds__(NT, 1)
void main_kernel(const float* __restrict__ f0,  const float* __restrict__ f1,
                 const float* __restrict__ f2,  const float* __restrict__ f3,
                 const float* __restrict__ attrs,
                 const float* __restrict__ W1_0, const float* __restrict__ W2_0,
                 const float* __restrict__ Wl0,  const float* __restrict__ sc0,
                 const float* __restrict__ W1_1, const float* __restrict__ W2_1,
                 const float* __restrict__ Wl1,  const float* __restrict__ sc1,
                 const float* __restrict__ W1_2, const float* __restrict__ W2_2,
                 const float* __restrict__ Wl2,  const float* __restrict__ sc2,
                 float* __restrict__ out, int B) {
    extern __shared__ float S[];
    float* tabS = S;            // 13760 floats
    float* xS   = S + 13760;    // 40960 floats

    const int tid = threadIdx.x;
    const int g   = tid >> 6;        // b-group 0..7
    const int c   = tid & 63;        // channel
    const int b0  = blockIdx.x * NB + g * NBSUB;

    // cooperative copy of the packed table into smem
    {
        const float4* gt4 = (const float4*)g_table;
        float4* tp4 = (float4*)tabS;
#pragma unroll
        for (int k = 0; k < 7; k++) {
            int idx = k * NT + tid;
            if (idx < NROWS * TS / 4) tp4[idx] = gt4[idx];
        }
    }

    // gather x for 2 b's: xS[i*1024 + tid*2 + s]
#pragma unroll
    for (int s = 0; s < NBSUB; s++) {
        int bb = b0 + s; if (bb >= B) bb = B - 1;
        const int base = bb * 64 + c;
        xS[tid * 2 + s] = f0[base];
#pragma unroll
        for (int k = 0; k < 3; k++)
            xS[(1 + k) * 1024 + tid * 2 + s]  = f1[base * 3 + k];
#pragma unroll
        for (int k = 0; k < 9; k++)
            xS[(4 + k) * 1024 + tid * 2 + s]  = f2[base * 9 + k];
#pragma unroll
        for (int k = 0; k < 27; k++)
            xS[(13 + k) * 1024 + tid * 2 + s] = f3[base * 27 + k];
    }

    // element-aware channel weights for both b's
    float w1v[NBSUB][3], w2v[NBSUB][3];
#pragma unroll
    for (int s = 0; s < NBSUB; s++) {
        int bb = b0 + s; if (bb >= B) bb = B - 1;
        float a10 = 0.f, a11 = 0.f, a12 = 0.f, a20 = 0.f, a21 = 0.f, a22 = 0.f;
#pragma unroll
        for (int e = 0; e < 10; e++) {
            float a = __ldg(&attrs[bb * 10 + e]);
            a10 += a * __ldg(&W1_0[e * 64 + c]);
            a20 += a * __ldg(&W2_0[e * 64 + c]);
            a11 += a * __ldg(&W1_1[e * 64 + c]);
            a21 += a * __ldg(&W2_1[e * 64 + c]);
            a12 += a * __ldg(&W1_2[e * 64 + c]);
            a22 += a * __ldg(&W2_2[e * 64 + c]);
        }
        w1v[s][0] = a10; w1v[s][1] = a11; w1v[s][2] = a12;
        w2v[s][0] = a20; w2v[s][1] = a21; w2v[s][2] = a22;
    }
    __syncthreads();

    const char* xb = (const char*)xS + tid * 8;

    // ---- phase A: a2[s][m] = sum_pairs u[p][m] * x_i[s] * x_j[s] ----
    unsigned long long a2[NBSUB][7];
#pragma unroll
    for (int s = 0; s < NBSUB; s++)
#pragma unroll
        for (int k = 0; k < 7; k++) a2[s][k] = 0ull;

    const ulonglong2* trow = (const ulonglong2*)tabS;
#pragma unroll 2
    for (int p = 0; p < NPAIR; p++, trow += 4) {
        ulonglong2 q0 = trow[0];
        ulonglong2 q1 = trow[1];
        ulonglong2 q2 = trow[2];
        ulonglong2 q3 = trow[3];
        unsigned int io = (unsigned int)(q3.y);
        unsigned int jo = (unsigned int)(q3.y >> 32);
        float2 xi = *(const float2*)(xb + io);
        float2 xj = *(const float2*)(xb + jo);
        unsigned long long y0 = dup2(xi.x * xj.x);
        unsigned long long y1 = dup2(xi.y * xj.y);
        fma2(a2[0][0], q0.x, y0); fma2(a2[1][0], q0.x, y1);
        fma2(a2[0][1], q0.y, y0); fma2(a2[1][1], q0.y, y1);
        fma2(a2[0][2], q1.x, y0); fma2(a2[1][2], q1.x, y1);
        fma2(a2[0][3], q1.y, y0); fma2(a2[1][3], q1.y, y1);
        fma2(a2[0][4], q2.x, y0); fma2(a2[1][4], q2.x, y1);
        fma2(a2[0][5], q2.y, y0); fma2(a2[1][5], q2.y, y1);
        fma2(a2[0][6], q3.x, y0); fma2(a2[1][6], q3.x, y1);
    }

    // ---- phase B: a1[s][m] = U1[m,:] . x[s] ----
    unsigned long long a1[NBSUB][7];
#pragma unroll
    for (int s = 0; s < NBSUB; s++)
#pragma unroll
        for (int k = 0; k < 7; k++) a1[s][k] = 0ull;

#pragma unroll 2
    for (int r = 0; r < DIM; r++, trow += 4) {
        ulonglong2 q0 = trow[0];
        ulonglong2 q1 = trow[1];
        ulonglong2 q2 = trow[2];
        ulonglong2 q3 = trow[3];
        unsigned int io = (unsigned int)(q3.y);
        float2 xi = *(const float2*)(xb + io);
        unsigned long long y0 = dup2(xi.x);
        unsigned long long y1 = dup2(xi.y);
        fma2(a1[0][0], q0.x, y0); fma2(a1[1][0], q0.x, y1);
        fma2(a1[0][1], q0.y, y0); fma2(a1[1][1], q0.y, y1);
        fma2(a1[0][2], q1.x, y0); fma2(a1[1][2], q1.x, y1);
        fma2(a1[0][3], q1.y, y0); fma2(a1[1][3], q1.y, y1);
        fma2(a1[0][4], q2.x, y0); fma2(a1[1][4], q2.x, y1);
        fma2(a1[0][5], q2.y, y0); fma2(a1[1][5], q2.y, y1);
        fma2(a1[0][6], q3.x, y0); fma2(a1[1][6], q3.x, y1);
    }

    __syncthreads();   // everyone done reading xS before we overwrite it

    // reuse xS region: basis[16 b][64 c][20] + Wlin cache
    float* basS = xS;                       // 20480 floats
    float* wlS  = xS + 20480;               // 12288 floats

    const int LSEL[14] = {0, 1, 1, 1, 2, 2, 2, 2, 2, 2, 2, 2, 2, 0};
#pragma unroll
    for (int s = 0; s < NBSUB; s++) {
        float* bs = basS + ((g * NBSUB + s) * 64 + c) * BSTRIDE;
#pragma unroll
        for (int k = 0; k < 7; k++) {
            float2 v2 = unpk2(a2[s][k]);
            float2 v1 = unpk2(a1[s][k]);
            int m0 = 2 * k, m1 = 2 * k + 1;
            bs[m0] = v1.x * w1v[s][LSEL[m0]] + v2.x * w2v[s][LSEL[m0]];
            if (m1 < 13)
                bs[m1] = v1.y * w1v[s][LSEL[m1]] + v2.y * w2v[s][LSEL[m1]];
        }
    }

    // Wlin cache: wlS[l*4096 + cc*64 + o]
    {
        const float4* a0p = (const float4*)Wl0;
        const float4* a1p = (const float4*)Wl1;
        const float4* a2p = (const float4*)Wl2;
        float4* w4 = (float4*)wlS;
#pragma unroll
        for (int k = 0; k < 2; k++) {
            int idx = k * NT + tid;
            w4[idx]        = a0p[idx];
            w4[1024 + idx] = a1p[idx];
            w4[2048 + idx] = a2p[idx];
        }
    }
    __syncthreads();

    // ---- self-interaction: r[s][m] = sum_cc basis[b_s][cc][m] * Wlin_l[cc][c] ----
    float r[NBSUB][13];
#pragma unroll
    for (int s = 0; s < NBSUB; s++)
#pragma unroll
        for (int m = 0; m < 13; m++) r[s][m] = 0.0f;

#pragma unroll 2
    for (int cc = 0; cc < 64; cc++) {
        float wv0 = wlS[cc * 64 + c];
        float wv1 = wlS[4096 + cc * 64 + c];
        float wv2 = wlS[8192 + cc * 64 + c];
#pragma unroll
        for (int s = 0; s < NBSUB; s++) {
            const float* br = basS + ((g * NBSUB + s) * 64 + cc) * BSTRIDE;
            float4 q0 = *(const float4*)(br);
            float4 q1 = *(const float4*)(br + 4);
            float4 q2 = *(const float4*)(br + 8);
            float b12 = br[12];
            r[s][0]  += q0.x * wv0;
            r[s][1]  += q0.y * wv1;
            r[s][2]  += q0.z * wv1;
            r[s][3]  += q0.w * wv1;
            r[s][4]  += q1.x * wv2;
            r[s][5]  += q1.y * wv2;
            r[s][6]  += q1.z * wv2;
            r[s][7]  += q1.w * wv2;
            r[s][8]  += q2.x * wv2;
            r[s][9]  += q2.y * wv2;
            r[s][10] += q2.z * wv2;
            r[s][11] += q2.w * wv2;
            r[s][12] += b12  * wv2;
        }
    }

    // ---- outputs: concat [out0 (B,C)] [out1 (B,C,3)] [out2 (B,C,9)] ----
    float* o0 = out;
    float* o1 = out + (size_t)B * 64;
    float* o2 = out + (size_t)B * 64 * 4;
#pragma unroll
    for (int s = 0; s < NBSUB; s++) {
        int bb = b0 + s;
        if (bb >= B) break;
        const int bo = bb * 64 + c;
        o0[bo] = r[s][0] + __ldg(&sc0[bo]);
#pragma unroll
        for (int k = 0; k < 3; k++)
            o1[bo * 3 + k] = r[s][1 + k] + __ldg(&sc1[bo * 3 + k]);
#pragma unroll
        for (int k = 0; k < 9; k++)
            o2[bo * 9 + k] = r[s][4 + k] + __ldg(&sc2[bo * 9 + k]);
    }
}

extern "C" void kernel_launch(void* const* d_in, const int* in_sizes, int n_in,
                              void* d_out, int out_size) {
    const float* f0    = (const float*)d_in[0];
    const float* f1    = (const float*)d_in[1];
    const float* f2    = (const float*)d_in[2];
    const float* f3    = (const float*)d_in[3];
    const float* attrs = (const float*)d_in[4];
    const float* U2_0  = (const float*)d_in[5];
    const float* U1_0  = (const float*)d_in[6];
    const float* W1_0  = (const float*)d_in[7];
    const float* W2_0  = (const float*)d_in[8];
    const float* Wl0   = (const float*)d_in[9];
    const float* sc0   = (const float*)d_in[10];
    const float* U2_1  = (const float*)d_in[11];
    const float* U1_1  = (const float*)d_in[12];
    const float* W1_1  = (const float*)d_in[13];
    const float* W2_1  = (const float*)d_in[14];
    const float* Wl1   = (const float*)d_in[15];
    const float* sc1   = (const float*)d_in[16];
    const float* U2_2  = (const float*)d_in[17];
    const float* U1_2  = (const float*)d_in[18];
    const float* W1_2  = (const float*)d_in[19];
    const float* W2_2  = (const float*)d_in[20];
    const float* Wl2   = (const float*)d_in[21];
    const float* sc2   = (const float*)d_in[22];

    const int B = in_sizes[0] / 64;

    cudaFuncSetAttribute(main_kernel,
                         cudaFuncAttributeMaxDynamicSharedMemorySize, SMEM_BYTES);

    prep_kernel<<<(NROWS + 255) / 256, 256>>>(U2_0, U1_0, U2_1, U1_1, U2_2, U1_2);

    const int grid = (B + NB - 1) / NB;
    main_kernel<<<grid, NT, SMEM_BYTES>>>(f0, f1, f2, f3, attrs,
                                          W1_0, W2_0, Wl0, sc0,
                                          W1_1, W2_1, Wl1, sc1,
                                          W1_2, W2_2, Wl2, sc2,
                                          (float*)d_out, B);
}

// round 6
// speedup vs baseline: 2.0788x; 1.0342x over previous
#include <cuda_runtime.h>
#include <stdint.h>

// Problem constants
#define NT    512      // threads per CTA (8 groups x 64 channels)
#define NBSUB 2        // b-values per thread
#define NB    16       // b-values per CTA
#define DIM   40
#define NPAIR 820      // DIM*(DIM+1)/2 unique symmetric pairs
#define NROWS 860      // pairs + 40 U1 rows
#define TS    16       // table row stride (floats)
#define XROWB 4096     // x_s row stride in bytes (512 threads * 8B)

// Packed coefficient table, ROW-MAJOR TRIANGULAR order (i outer, j from i):
//  rows [0,820): per pair (i<=j): 13 symmetric-folded U2 coeffs (off-diag doubled), 3 pad
//  rows [820,860): per i: 13 U1 coeffs, 3 pad
__device__ float g_table[NROWS * TS];

__global__ void prep_kernel(const float* __restrict__ U2_0,
                            const float* __restrict__ U1_0,
                            const float* __restrict__ U2_1,
                            const float* __restrict__ U1_1,
                            const float* __restrict__ U2_2,
                            const float* __restrict__ U1_2) {
    int idx = blockIdx.x * blockDim.x + threadIdx.x;
    if (idx >= NROWS) return;
    float row[TS];
#pragma unroll
    for (int k = 0; k < TS; k++) row[k] = 0.0f;

    if (idx < NPAIR) {
        // invert p -> (i, j) for row-major triangular order (i outer, j from i)
        int rem = idx;
        int i = 0;
        while (rem >= DIM - i) { rem -= DIM - i; i++; }
        int j = i + rem;
        const float* U2b[3] = {U2_0, U2_1, U2_2};
#pragma unroll
        for (int m = 0; m < 13; m++) {
            int l  = (m == 0) ? 0 : ((m < 4) ? 1 : 2);
            int mm = (m == 0) ? 0 : ((m < 4) ? (m - 1) : (m - 4));
            const float* U = U2b[l];
            float v = U[(mm * DIM + i) * DIM + j];
            if (i != j) v += U[(mm * DIM + j) * DIM + i];
            row[m] = v;
        }
    } else {
        int i = idx - NPAIR;
        const float* U1b[3] = {U1_0, U1_1, U1_2};
#pragma unroll
        for (int m = 0; m < 13; m++) {
            int l  = (m == 0) ? 0 : ((m < 4) ? 1 : 2);
            int mm = (m == 0) ? 0 : ((m < 4) ? (m - 1) : (m - 4));
            row[m] = U1b[l][mm * DIM + i];
        }
    }
#pragma unroll
    for (int k = 0; k < TS; k++) g_table[idx * TS + k] = row[k];
}

// ---- packed f32x2 helpers ----
__device__ __forceinline__ void fma2(unsigned long long& acc,
                                     unsigned long long u,
                                     unsigned long long y) {
    asm("fma.rn.f32x2 %0, %1, %2, %0;" : "+l"(acc) : "l"(u), "l"(y));
}
__device__ __forceinline__ unsigned long long dup2(float y) {
    unsigned long long r;
    asm("mov.b64 %0, {%1, %1};" : "=l"(r) : "f"(y));
    return r;
}
__device__ __forceinline__ float2 unpk2(unsigned long long v) {
    float2 r;
    asm("mov.b64 {%0, %1}, %2;" : "=f"(r.x), "=f"(r.y) : "l"(v));
    return r;
}

// SMEM layout (floats):
//   [0,     13760)  coeff table (55 KB)
//   [13760, 54720)  xS: x[40][512 threads][2 b]  (160 KB)
//                   reused after phases: basis[16][64][20] (80 KB) + Wlin (48 KB)
#define SMEM_FLOATS 54720
#define SMEM_BYTES  (SMEM_FLOATS * 4)
#define BSTRIDE 20     // basis row stride in floats

__global__ __launch_bounds__(NT, 1)
void main_kernel(const float* __restrict__ f0,  const float* __restrict__ f1,
                 const float* __restrict__ f2,  const float* __restrict__ f3,
                 const float* __restrict__ attrs,
                 const float* __restrict__ W1_0, const float* __restrict__ W2_0,
                 const float* __restrict__ Wl0,  const float* __restrict__ sc0,
                 const float* __restrict__ W1_1, const float* __restrict__ W2_1,
                 const float* __restrict__ Wl1,  const float* __restrict__ sc1,
                 const float* __restrict__ W1_2, const float* __restrict__ W2_2,
                 const float* __restrict__ Wl2,  const float* __restrict__ sc2,
                 float* __restrict__ out, int B) {
    extern __shared__ float S[];
    float* tabS = S;            // 13760 floats
    float* xS   = S + 13760;    // 40960 floats

    const int tid = threadIdx.x;
    const int g   = tid >> 6;        // b-group 0..7
    const int c   = tid & 63;        // channel
    const int b0  = blockIdx.x * NB + g * NBSUB;

    // cooperative copy of the packed table into smem
    {
        const float4* gt4 = (const float4*)g_table;
        float4* tp4 = (float4*)tabS;
#pragma unroll
        for (int k = 0; k < 7; k++) {
            int idx = k * NT + tid;
            if (idx < NROWS * TS / 4) tp4[idx] = gt4[idx];
        }
    }

    // gather x for 2 b's: xS[i*1024 + tid*2 + s]
#pragma unroll
    for (int s = 0; s < NBSUB; s++) {
        int bb = b0 + s; if (bb >= B) bb = B - 1;
        const int base = bb * 64 + c;
        xS[tid * 2 + s] = f0[base];
#pragma unroll
        for (int k = 0; k < 3; k++)
            xS[(1 + k) * 1024 + tid * 2 + s]  = f1[base * 3 + k];
#pragma unroll
        for (int k = 0; k < 9; k++)
            xS[(4 + k) * 1024 + tid * 2 + s]  = f2[base * 9 + k];
#pragma unroll
        for (int k = 0; k < 27; k++)
            xS[(13 + k) * 1024 + tid * 2 + s] = f3[base * 27 + k];
    }

    // element-aware channel weights for both b's
    float w1v[NBSUB][3], w2v[NBSUB][3];
#pragma unroll
    for (int s = 0; s < NBSUB; s++) {
        int bb = b0 + s; if (bb >= B) bb = B - 1;
        float a10 = 0.f, a11 = 0.f, a12 = 0.f, a20 = 0.f, a21 = 0.f, a22 = 0.f;
#pragma unroll
        for (int e = 0; e < 10; e++) {
            float a = __ldg(&attrs[bb * 10 + e]);
            a10 += a * __ldg(&W1_0[e * 64 + c]);
            a20 += a * __ldg(&W2_0[e * 64 + c]);
            a11 += a * __ldg(&W1_1[e * 64 + c]);
            a21 += a * __ldg(&W2_1[e * 64 + c]);
            a12 += a * __ldg(&W1_2[e * 64 + c]);
            a22 += a * __ldg(&W2_2[e * 64 + c]);
        }
        w1v[s][0] = a10; w1v[s][1] = a11; w1v[s][2] = a12;
        w2v[s][0] = a20; w2v[s][1] = a21; w2v[s][2] = a22;
    }
    __syncthreads();

    // ---- phase A: a2[s][m] = sum_{i<=j} u[p][m] * x_i[s] * x_j[s] ----
    // i-major: xi loaded once per i-row; xj walks forward; table walks rows.
    unsigned long long a2[NBSUB][7];
#pragma unroll
    for (int s = 0; s < NBSUB; s++)
#pragma unroll
        for (int k = 0; k < 7; k++) a2[s][k] = 0ull;

    const ulonglong2* trow = (const ulonglong2*)tabS;
    const char* xtb = (const char*)xS + tid * 8;

    for (int i = 0; i < DIM; i++) {
        const float2 xi = *(const float2*)(xtb + i * XROWB);
        const char* xjp = xtb + i * XROWB;
#pragma unroll 2
        for (int j = i; j < DIM; j++) {
            ulonglong2 q0 = trow[0];
            ulonglong2 q1 = trow[1];
            ulonglong2 q2 = trow[2];
            ulonglong2 q3 = trow[3];
            trow += 4;
            float2 xj = *(const float2*)xjp;
            xjp += XROWB;
            unsigned long long y0 = dup2(xi.x * xj.x);
            unsigned long long y1 = dup2(xi.y * xj.y);
            fma2(a2[0][0], q0.x, y0); fma2(a2[1][0], q0.x, y1);
            fma2(a2[0][1], q0.y, y0); fma2(a2[1][1], q0.y, y1);
            fma2(a2[0][2], q1.x, y0); fma2(a2[1][2], q1.x, y1);
            fma2(a2[0][3], q1.y, y0); fma2(a2[1][3], q1.y, y1);
            fma2(a2[0][4], q2.x, y0); fma2(a2[1][4], q2.x, y1);
            fma2(a2[0][5], q2.y, y0); fma2(a2[1][5], q2.y, y1);
            fma2(a2[0][6], q3.x, y0); fma2(a2[1][6], q3.x, y1);
        }
    }

    // ---- phase B: a1[s][m] = U1[m,:] . x[s] ----
    unsigned long long a1[NBSUB][7];
#pragma unroll
    for (int s = 0; s < NBSUB; s++)
#pragma unroll
        for (int k = 0; k < 7; k++) a1[s][k] = 0ull;

#pragma unroll 2
    for (int i = 0; i < DIM; i++, trow += 4) {
        ulonglong2 q0 = trow[0];
        ulonglong2 q1 = trow[1];
        ulonglong2 q2 = trow[2];
        ulonglong2 q3 = trow[3];
        float2 xi = *(const float2*)(xtb + i * XROWB);
        unsigned long long y0 = dup2(xi.x);
        unsigned long long y1 = dup2(xi.y);
        fma2(a1[0][0], q0.x, y0); fma2(a1[1][0], q0.x, y1);
        fma2(a1[0][1], q0.y, y0); fma2(a1[1][1], q0.y, y1);
        fma2(a1[0][2], q1.x, y0); fma2(a1[1][2], q1.x, y1);
        fma2(a1[0][3], q1.y, y0); fma2(a1[1][3], q1.y, y1);
        fma2(a1[0][4], q2.x, y0); fma2(a1[1][4], q2.x, y1);
        fma2(a1[0][5], q2.y, y0); fma2(a1[1][5], q2.y, y1);
        fma2(a1[0][6], q3.x, y0); fma2(a1[1][6], q3.x, y1);
    }

    __syncthreads();   // everyone done reading xS before we overwrite it

    // reuse xS region: basis[16 b][64 c][20] + Wlin cache
    float* basS = xS;                       // 20480 floats
    float* wlS  = xS + 20480;               // 12288 floats

    const int LSEL[14] = {0, 1, 1, 1, 2, 2, 2, 2, 2, 2, 2, 2, 2, 0};
#pragma unroll
    for (int s = 0; s < NBSUB; s++) {
        float* bs = basS + ((g * NBSUB + s) * 64 + c) * BSTRIDE;
#pragma unroll
        for (int k = 0; k < 7; k++) {
            float2 v2 = unpk2(a2[s][k]);
            float2 v1 = unpk2(a1[s][k]);
            int m0 = 2 * k, m1 = 2 * k + 1;
            bs[m0] = v1.x * w1v[s][LSEL[m0]] + v2.x * w2v[s][LSEL[m0]];
            if (m1 < 13)
                bs[m1] = v1.y * w1v[s][LSEL[m1]] + v2.y * w2v[s][LSEL[m1]];
        }
    }

    // Wlin cache: wlS[l*4096 + cc*64 + o]
    {
        const float4* a0p = (const float4*)Wl0;
        const float4* a1p = (const float4*)Wl1;
        const float4* a2p = (const float4*)Wl2;
        float4* w4 = (float4*)wlS;
#pragma unroll
        for (int k = 0; k < 2; k++) {
            int idx = k * NT + tid;
            w4[idx]        = a0p[idx];
            w4[1024 + idx] = a1p[idx];
            w4[2048 + idx] = a2p[idx];
        }
    }
    __syncthreads();

    // ---- self-interaction: r[s][m] = sum_cc basis[b_s][cc][m] * Wlin_l[cc][c] ----
    float r[NBSUB][13];
#pragma unroll
    for (int s = 0; s < NBSUB; s++)
#pragma unroll
        for (int m = 0; m < 13; m++) r[s][m] = 0.0f;

#pragma unroll 2
    for (int cc = 0; cc < 64; cc++) {
        float wv0 = wlS[cc * 64 + c];
        float wv1 = wlS[4096 + cc * 64 + c];
        float wv2 = wlS[8192 + cc * 64 + c];
#pragma unroll
        for (int s = 0; s < NBSUB; s++) {
            const float* br = basS + ((g * NBSUB + s) * 64 + cc) * BSTRIDE;
            float4 q0 = *(const float4*)(br);
            float4 q1 = *(const float4*)(br + 4);
            float4 q2 = *(const float4*)(br + 8);
            float b12 = br[12];
            r[s][0]  += q0.x * wv0;
            r[s][1]  += q0.y * wv1;
            r[s][2]  += q0.z * wv1;
            r[s][3]  += q0.w * wv1;
            r[s][4]  += q1.x * wv2;
            r[s][5]  += q1.y * wv2;
            r[s][6]  += q1.z * wv2;
            r[s][7]  += q1.w * wv2;
            r[s][8]  += q2.x * wv2;
            r[s][9]  += q2.y * wv2;
            r[s][10] += q2.z * wv2;
            r[s][11] += q2.w * wv2;
            r[s][12] += b12  * wv2;
        }
    }

    // ---- outputs: concat [out0 (B,C)] [out1 (B,C,3)] [out2 (B,C,9)] ----
    float* o0 = out;
    float* o1 = out + (size_t)B * 64;
    float* o2 = out + (size_t)B * 64 * 4;
#pragma unroll
    for (int s = 0; s < NBSUB; s++) {
        int bb = b0 + s;
        if (bb >= B) break;
        const int bo = bb * 64 + c;
        o0[bo] = r[s][0] + __ldg(&sc0[bo]);
#pragma unroll
        for (int k = 0; k < 3; k++)
            o1[bo * 3 + k] = r[s][1 + k] + __ldg(&sc1[bo * 3 + k]);
#pragma unroll
        for (int k = 0; k < 9; k++)
            o2[bo * 9 + k] = r[s][4 + k] + __ldg(&sc2[bo * 9 + k]);
    }
}

extern "C" void kernel_launch(void* const* d_in, const int* in_sizes, int n_in,
                              void* d_out, int out_size) {
    const float* f0    = (const float*)d_in[0];
    const float* f1    = (const float*)d_in[1];
    const float* f2    = (const float*)d_in[2];
    const float* f3    = (const float*)d_in[3];
    const float* attrs = (const float*)d_in[4];
    const float* U2_0  = (const float*)d_in[5];
    const float* U1_0  = (const float*)d_in[6];
    const float* W1_0  = (const float*)d_in[7];
    const float* W2_0  = (const float*)d_in[8];
    const float* Wl0   = (const float*)d_in[9];
    const float* sc0   = (const float*)d_in[10];
    const float* U2_1  = (const float*)d_in[11];
    const float* U1_1  = (const float*)d_in[12];
    const float* W1_1  = (const float*)d_in[13];
    const float* W2_1  = (const float*)d_in[14];
    const float* Wl1   = (const float*)d_in[15];
    const float* sc1   = (const float*)d_in[16];
    const float* U2_2  = (const float*)d_in[17];
    const float* U1_2  = (const float*)d_in[18];
    const float* W1_2  = (const float*)d_in[19];
    const float* W2_2  = (const float*)d_in[20];
    const float* Wl2   = (const float*)d_in[21];
    const float* sc2   = (const float*)d_in[22];

    const int B = in_sizes[0] / 64;

    cudaFuncSetAttribute(main_kernel,
                         cudaFuncAttributeMaxDynamicSharedMemorySize, SMEM_BYTES);

    prep_kernel<<<(NROWS + 255) / 256, 256>>>(U2_0, U1_0, U2_1, U1_1, U2_2, U1_2);

    const int grid = (B + NB - 1) / NB;
    main_kernel<<<grid, NT, SMEM_BYTES>>>(f0, f1, f2, f3, attrs,
                                          W1_0, W2_0, Wl0, sc0,
                                          W1_1, W2_1, Wl1, sc1,
                                          W1_2, W2_2, Wl2, sc2,
                                          (float*)d_out, B);
}

// round 7
// speedup vs baseline: 2.3083x; 1.1104x over previous
#include <cuda_runtime.h>
#include <stdint.h>

// Problem constants
#define NT    256      // threads per CTA (4 groups x 64 channels)
#define NBSUB 4        // b-values per thread
#define NB    16       // b-values per CTA
#define DIM   40
#define NPAIR 820      // DIM*(DIM+1)/2 unique symmetric pairs
#define NROWS 860      // pairs + 40 U1 rows
#define TS    16       // table row stride (floats)
#define XROWB 4096     // x row stride in bytes (256 threads * 16B)

// Packed coefficient table, ROW-MAJOR TRIANGULAR order (i outer, j from i):
//  rows [0,820): per pair (i<=j): 13 symmetric-folded U2 coeffs (off-diag doubled), 3 pad
//  rows [820,860): per i: 13 U1 coeffs, 3 pad
__device__ float g_table[NROWS * TS];

__global__ void prep_kernel(const float* __restrict__ U2_0,
                            const float* __restrict__ U1_0,
                            const float* __restrict__ U2_1,
                            const float* __restrict__ U1_1,
                            const float* __restrict__ U2_2,
                            const float* __restrict__ U1_2) {
    int idx = blockIdx.x * blockDim.x + threadIdx.x;
    if (idx >= NROWS) return;
    float row[TS];
#pragma unroll
    for (int k = 0; k < TS; k++) row[k] = 0.0f;

    if (idx < NPAIR) {
        // invert p -> (i, j) for row-major triangular order (i outer, j from i)
        int rem = idx;
        int i = 0;
        while (rem >= DIM - i) { rem -= DIM - i; i++; }
        int j = i + rem;
        const float* U2b[3] = {U2_0, U2_1, U2_2};
#pragma unroll
        for (int m = 0; m < 13; m++) {
            int l  = (m == 0) ? 0 : ((m < 4) ? 1 : 2);
            int mm = (m == 0) ? 0 : ((m < 4) ? (m - 1) : (m - 4));
            const float* U = U2b[l];
            float v = U[(mm * DIM + i) * DIM + j];
            if (i != j) v += U[(mm * DIM + j) * DIM + i];
            row[m] = v;
        }
    } else {
        int i = idx - NPAIR;
        const float* U1b[3] = {U1_0, U1_1, U1_2};
#pragma unroll
        for (int m = 0; m < 13; m++) {
            int l  = (m == 0) ? 0 : ((m < 4) ? 1 : 2);
            int mm = (m == 0) ? 0 : ((m < 4) ? (m - 1) : (m - 4));
            row[m] = U1b[l][mm * DIM + i];
        }
    }
#pragma unroll
    for (int k = 0; k < TS; k++) g_table[idx * TS + k] = row[k];
}

// ---- packed f32x2 helpers ----
__device__ __forceinline__ void fma2(unsigned long long& acc,
                                     unsigned long long u,
                                     unsigned long long y) {
    asm("fma.rn.f32x2 %0, %1, %2, %0;" : "+l"(acc) : "l"(u), "l"(y));
}
__device__ __forceinline__ unsigned long long dup2(float y) {
    unsigned long long r;
    asm("mov.b64 %0, {%1, %1};" : "=l"(r) : "f"(y));
    return r;
}
__device__ __forceinline__ float2 unpk2(unsigned long long v) {
    float2 r;
    asm("mov.b64 {%0, %1}, %2;" : "=f"(r.x), "=f"(r.y) : "l"(v));
    return r;
}

// SMEM layout (floats):
//   [0,     13760)  coeff table (55 KB)
//   [13760, 54720)  xS: x[40][256 threads][4 b]  (160 KB)
//                   reused after phases: basis[16][64][20] (80 KB) + Wlin (48 KB)
#define SMEM_FLOATS 54720
#define SMEM_BYTES  (SMEM_FLOATS * 4)
#define BSTRIDE 20     // basis row stride in floats

__global__ __launch_bounds__(NT, 1)
void main_kernel(const float* __restrict__ f0,  const float* __restrict__ f1,
                 const float* __restrict__ f2,  const float* __restrict__ f3,
                 const float* __restrict__ attrs,
                 const float* __restrict__ W1_0, const float* __restrict__ W2_0,
                 const float* __restrict__ Wl0,  const float* __restrict__ sc0,
                 const float* __restrict__ W1_1, const float* __restrict__ W2_1,
                 const float* __restrict__ Wl1,  const float* __restrict__ sc1,
                 const float* __restrict__ W1_2, const float* __restrict__ W2_2,
                 const float* __restrict__ Wl2,  const float* __restrict__ sc2,
                 float* __restrict__ out, int B) {
    extern __shared__ float S[];
    float* tabS = S;            // 13760 floats
    float* xS   = S + 13760;    // 40960 floats

    const int tid = threadIdx.x;
    const int g   = tid >> 6;        // b-group 0..3
    const int c   = tid & 63;        // channel
    const int b0  = blockIdx.x * NB + g * NBSUB;

    // cooperative copy of the packed table into smem
    {
        const float4* gt4 = (const float4*)g_table;
        float4* tp4 = (float4*)tabS;
#pragma unroll
        for (int k = 0; k < 14; k++) {
            int idx = k * NT + tid;
            if (idx < NROWS * TS / 4) tp4[idx] = gt4[idx];
        }
    }

    // gather x for 4 b's: xS[i*1024 + tid*4 + s]
#pragma unroll
    for (int s = 0; s < NBSUB; s++) {
        int bb = b0 + s; if (bb >= B) bb = B - 1;
        const int base = bb * 64 + c;
        xS[tid * 4 + s] = f0[base];
#pragma unroll
        for (int k = 0; k < 3; k++)
            xS[(1 + k) * 1024 + tid * 4 + s]  = f1[base * 3 + k];
#pragma unroll
        for (int k = 0; k < 9; k++)
            xS[(4 + k) * 1024 + tid * 4 + s]  = f2[base * 9 + k];
#pragma unroll
        for (int k = 0; k < 27; k++)
            xS[(13 + k) * 1024 + tid * 4 + s] = f3[base * 27 + k];
    }

    // element-aware channel weights for the 4 b's
    float w1v[NBSUB][3], w2v[NBSUB][3];
#pragma unroll
    for (int s = 0; s < NBSUB; s++) {
        int bb = b0 + s; if (bb >= B) bb = B - 1;
        float a10 = 0.f, a11 = 0.f, a12 = 0.f, a20 = 0.f, a21 = 0.f, a22 = 0.f;
#pragma unroll
        for (int e = 0; e < 10; e++) {
            float a = __ldg(&attrs[bb * 10 + e]);
            a10 += a * __ldg(&W1_0[e * 64 + c]);
            a20 += a * __ldg(&W2_0[e * 64 + c]);
            a11 += a * __ldg(&W1_1[e * 64 + c]);
            a21 += a * __ldg(&W2_1[e * 64 + c]);
            a12 += a * __ldg(&W1_2[e * 64 + c]);
            a22 += a * __ldg(&W2_2[e * 64 + c]);
        }
        w1v[s][0] = a10; w1v[s][1] = a11; w1v[s][2] = a12;
        w2v[s][0] = a20; w2v[s][1] = a21; w2v[s][2] = a22;
    }
    __syncthreads();

    // ---- phase A: a2[s][m] = sum_{i<=j} u[p][m] * x_i[s] * x_j[s] ----
    unsigned long long a2[NBSUB][7];
#pragma unroll
    for (int s = 0; s < NBSUB; s++)
#pragma unroll
        for (int k = 0; k < 7; k++) a2[s][k] = 0ull;

    const ulonglong2* trow = (const ulonglong2*)tabS;
    const char* xtb = (const char*)xS + tid * 16;

    for (int i = 0; i < DIM; i++) {
        const float4 xi = *(const float4*)(xtb + i * XROWB);
        const char* xjp = xtb + i * XROWB;
#pragma unroll 2
        for (int j = i; j < DIM; j++) {
            ulonglong2 q0 = trow[0];
            ulonglong2 q1 = trow[1];
            ulonglong2 q2 = trow[2];
            ulonglong2 q3 = trow[3];
            trow += 4;
            float4 xj = *(const float4*)xjp;
            xjp += XROWB;
            unsigned long long y0 = dup2(xi.x * xj.x);
            unsigned long long y1 = dup2(xi.y * xj.y);
            unsigned long long y2 = dup2(xi.z * xj.z);
            unsigned long long y3 = dup2(xi.w * xj.w);
            fma2(a2[0][0], q0.x, y0); fma2(a2[1][0], q0.x, y1);
            fma2(a2[2][0], q0.x, y2); fma2(a2[3][0], q0.x, y3);
            fma2(a2[0][1], q0.y, y0); fma2(a2[1][1], q0.y, y1);
            fma2(a2[2][1], q0.y, y2); fma2(a2[3][1], q0.y, y3);
            fma2(a2[0][2], q1.x, y0); fma2(a2[1][2], q1.x, y1);
            fma2(a2[2][2], q1.x, y2); fma2(a2[3][2], q1.x, y3);
            fma2(a2[0][3], q1.y, y0); fma2(a2[1][3], q1.y, y1);
            fma2(a2[2][3], q1.y, y2); fma2(a2[3][3], q1.y, y3);
            fma2(a2[0][4], q2.x, y0); fma2(a2[1][4], q2.x, y1);
            fma2(a2[2][4], q2.x, y2); fma2(a2[3][4], q2.x, y3);
            fma2(a2[0][5], q2.y, y0); fma2(a2[1][5], q2.y, y1);
            fma2(a2[2][5], q2.y, y2); fma2(a2[3][5], q2.y, y3);
            fma2(a2[0][6], q3.x, y0); fma2(a2[1][6], q3.x, y1);
            fma2(a2[2][6], q3.x, y2); fma2(a2[3][6], q3.x, y3);
        }
    }

    // ---- phase B: a1[s][m] = U1[m,:] . x[s] ----
    unsigned long long a1[NBSUB][7];
#pragma unroll
    for (int s = 0; s < NBSUB; s++)
#pragma unroll
        for (int k = 0; k < 7; k++) a1[s][k] = 0ull;

#pragma unroll 2
    for (int i = 0; i < DIM; i++, trow += 4) {
        ulonglong2 q0 = trow[0];
        ulonglong2 q1 = trow[1];
        ulonglong2 q2 = trow[2];
        ulonglong2 q3 = trow[3];
        float4 xi = *(const float4*)(xtb + i * XROWB);
        unsigned long long y0 = dup2(xi.x);
        unsigned long long y1 = dup2(xi.y);
        unsigned long long y2 = dup2(xi.z);
        unsigned long long y3 = dup2(xi.w);
        fma2(a1[0][0], q0.x, y0); fma2(a1[1][0], q0.x, y1);
        fma2(a1[2][0], q0.x, y2); fma2(a1[3][0], q0.x, y3);
        fma2(a1[0][1], q0.y, y0); fma2(a1[1][1], q0.y, y1);
        fma2(a1[2][1], q0.y, y2); fma2(a1[3][1], q0.y, y3);
        fma2(a1[0][2], q1.x, y0); fma2(a1[1][2], q1.x, y1);
        fma2(a1[2][2], q1.x, y2); fma2(a1[3][2], q1.x, y3);
        fma2(a1[0][3], q1.y, y0); fma2(a1[1][3], q1.y, y1);
        fma2(a1[2][3], q1.y, y2); fma2(a1[3][3], q1.y, y3);
        fma2(a1[0][4], q2.x, y0); fma2(a1[1][4], q2.x, y1);
        fma2(a1[2][4], q2.x, y2); fma2(a1[3][4], q2.x, y3);
        fma2(a1[0][5], q2.y, y0); fma2(a1[1][5], q2.y, y1);
        fma2(a1[2][5], q2.y, y2); fma2(a1[3][5], q2.y, y3);
        fma2(a1[0][6], q3.x, y0); fma2(a1[1][6], q3.x, y1);
        fma2(a1[2][6], q3.x, y2); fma2(a1[3][6], q3.x, y3);
    }

    __syncthreads();   // everyone done reading xS before we overwrite it

    // reuse xS region: basis[16 b][64 c][20] + Wlin cache
    float* basS = xS;                       // 20480 floats
    float* wlS  = xS + 20480;               // 12288 floats

    const int LSEL[14] = {0, 1, 1, 1, 2, 2, 2, 2, 2, 2, 2, 2, 2, 0};
#pragma unroll
    for (int s = 0; s < NBSUB; s++) {
        float* bs = basS + ((g * NBSUB + s) * 64 + c) * BSTRIDE;
#pragma unroll
        for (int k = 0; k < 7; k++) {
            float2 v2 = unpk2(a2[s][k]);
            float2 v1 = unpk2(a1[s][k]);
            int m0 = 2 * k, m1 = 2 * k + 1;
            bs[m0] = v1.x * w1v[s][LSEL[m0]] + v2.x * w2v[s][LSEL[m0]];
            if (m1 < 13)
                bs[m1] = v1.y * w1v[s][LSEL[m1]] + v2.y * w2v[s][LSEL[m1]];
        }
    }

    // Wlin cache: wlS[l*4096 + cc*64 + o]
    {
        const float4* a0p = (const float4*)Wl0;
        const float4* a1p = (const float4*)Wl1;
        const float4* a2p = (const float4*)Wl2;
        float4* w4 = (float4*)wlS;
#pragma unroll
        for (int k = 0; k < 4; k++) {
            int idx = k * NT + tid;
            w4[idx]        = a0p[idx];
            w4[1024 + idx] = a1p[idx];
            w4[2048 + idx] = a2p[idx];
        }
    }
    __syncthreads();

    // ---- self-interaction: r[s][m] = sum_cc basis[b_s][cc][m] * Wlin_l[cc][c] ----
    float r[NBSUB][13];
#pragma unroll
    for (int s = 0; s < NBSUB; s++)
#pragma unroll
        for (int m = 0; m < 13; m++) r[s][m] = 0.0f;

#pragma unroll 2
    for (int cc = 0; cc < 64; cc++) {
        float wv0 = wlS[cc * 64 + c];
        float wv1 = wlS[4096 + cc * 64 + c];
        float wv2 = wlS[8192 + cc * 64 + c];
#pragma unroll
        for (int s = 0; s < NBSUB; s++) {
            const float* br = basS + ((g * NBSUB + s) * 64 + cc) * BSTRIDE;
            float4 q0 = *(const float4*)(br);
            float4 q1 = *(const float4*)(br + 4);
            float4 q2 = *(const float4*)(br + 8);
            float b12 = br[12];
            r[s][0]  += q0.x * wv0;
            r[s][1]  += q0.y * wv1;
            r[s][2]  += q0.z * wv1;
            r[s][3]  += q0.w * wv1;
            r[s][4]  += q1.x * wv2;
            r[s][5]  += q1.y * wv2;
            r[s][6]  += q1.z * wv2;
            r[s][7]  += q1.w * wv2;
            r[s][8]  += q2.x * wv2;
            r[s][9]  += q2.y * wv2;
            r[s][10] += q2.z * wv2;
            r[s][11] += q2.w * wv2;
            r[s][12] += b12  * wv2;
        }
    }

    // ---- outputs: concat [out0 (B,C)] [out1 (B,C,3)] [out2 (B,C,9)] ----
    float* o0 = out;
    float* o1 = out + (size_t)B * 64;
    float* o2 = out + (size_t)B * 64 * 4;
#pragma unroll
    for (int s = 0; s < NBSUB; s++) {
        int bb = b0 + s;
        if (bb >= B) break;
        const int bo = bb * 64 + c;
        o0[bo] = r[s][0] + __ldg(&sc0[bo]);
#pragma unroll
        for (int k = 0; k < 3; k++)
            o1[bo * 3 + k] = r[s][1 + k] + __ldg(&sc1[bo * 3 + k]);
#pragma unroll
        for (int k = 0; k < 9; k++)
            o2[bo * 9 + k] = r[s][4 + k] + __ldg(&sc2[bo * 9 + k]);
    }
}

extern "C" void kernel_launch(void* const* d_in, const int* in_sizes, int n_in,
                              void* d_out, int out_size) {
    const float* f0    = (const float*)d_in[0];
    const float* f1    = (const float*)d_in[1];
    const float* f2    = (const float*)d_in[2];
    const float* f3    = (const float*)d_in[3];
    const float* attrs = (const float*)d_in[4];
    const float* U2_0  = (const float*)d_in[5];
    const float* U1_0  = (const float*)d_in[6];
    const float* W1_0  = (const float*)d_in[7];
    const float* W2_0  = (const float*)d_in[8];
    const float* Wl0   = (const float*)d_in[9];
    const float* sc0   = (const float*)d_in[10];
    const float* U2_1  = (const float*)d_in[11];
    const float* U1_1  = (const float*)d_in[12];
    const float* W1_1  = (const float*)d_in[13];
    const float* W2_1  = (const float*)d_in[14];
    const float* Wl1   = (const float*)d_in[15];
    const float* sc1   = (const float*)d_in[16];
    const float* U2_2  = (const float*)d_in[17];
    const float* U1_2  = (const float*)d_in[18];
    const float* W1_2  = (const float*)d_in[19];
    const float* W2_2  = (const float*)d_in[20];
    const float* Wl2   = (const float*)d_in[21];
    const float* sc2   = (const float*)d_in[22];

    const int B = in_sizes[0] / 64;

    cudaFuncSetAttribute(main_kernel,
                         cudaFuncAttributeMaxDynamicSharedMemorySize, SMEM_BYTES);

    prep_kernel<<<(NROWS + 255) / 256, 256>>>(U2_0, U1_0, U2_1, U1_1, U2_2, U1_2);

    const int grid = (B + NB - 1) / NB;
    main_kernel<<<grid, NT, SMEM_BYTES>>>(f0, f1, f2, f3, attrs,
                                          W1_0, W2_0, Wl0, sc0,
                                          W1_1, W2_1, Wl1, sc1,
                                          W1_2, W2_2, Wl2, sc2,
                                          (float*)d_out, B);
}

// round 8
// speedup vs baseline: 2.3205x; 1.0053x over previous
#include <cuda_runtime.h>
#include <stdint.h>

// Problem constants
#define NT    256      // threads per CTA (4 groups x 64 channels)
#define NBSUB 4        // b-values per thread
#define NB    16       // b-values per CTA
#define DIM   40
#define NPAIR 820      // DIM*(DIM+1)/2 unique symmetric pairs
#define NROWS 860      // pairs + 40 U1 rows
#define TS    16       // table row stride (floats)
#define XROWB 4096     // x row stride in bytes (256 threads * 16B)

// Packed coefficient table, ROW-MAJOR TRIANGULAR order (i outer, j from i):
//  rows [0,820): per pair (i<=j): 13 symmetric-folded U2 coeffs (off-diag doubled), 3 pad
//  rows [820,860): per i: 13 U1 coeffs, 3 pad
__device__ float g_table[NROWS * TS];

__global__ void prep_kernel(const float* __restrict__ U2_0,
                            const float* __restrict__ U1_0,
                            const float* __restrict__ U2_1,
                            const float* __restrict__ U1_1,
                            const float* __restrict__ U2_2,
                            const float* __restrict__ U1_2) {
    int idx = blockIdx.x * blockDim.x + threadIdx.x;
    if (idx >= NROWS) return;
    float row[TS];
#pragma unroll
    for (int k = 0; k < TS; k++) row[k] = 0.0f;

    if (idx < NPAIR) {
        // invert p -> (i, j) for row-major triangular order (i outer, j from i)
        int rem = idx;
        int i = 0;
        while (rem >= DIM - i) { rem -= DIM - i; i++; }
        int j = i + rem;
        const float* U2b[3] = {U2_0, U2_1, U2_2};
#pragma unroll
        for (int m = 0; m < 13; m++) {
            int l  = (m == 0) ? 0 : ((m < 4) ? 1 : 2);
            int mm = (m == 0) ? 0 : ((m < 4) ? (m - 1) : (m - 4));
            const float* U = U2b[l];
            float v = U[(mm * DIM + i) * DIM + j];
            if (i != j) v += U[(mm * DIM + j) * DIM + i];
            row[m] = v;
        }
    } else {
        int i = idx - NPAIR;
        const float* U1b[3] = {U1_0, U1_1, U1_2};
#pragma unroll
        for (int m = 0; m < 13; m++) {
            int l  = (m == 0) ? 0 : ((m < 4) ? 1 : 2);
            int mm = (m == 0) ? 0 : ((m < 4) ? (m - 1) : (m - 4));
            row[m] = U1b[l][mm * DIM + i];
        }
    }
#pragma unroll
    for (int k = 0; k < TS; k++) g_table[idx * TS + k] = row[k];
}

// ---- packed f32x2 helpers ----
__device__ __forceinline__ void fma2(unsigned long long& acc,
                                     unsigned long long u,
                                     unsigned long long y) {
    asm("fma.rn.f32x2 %0, %1, %2, %0;" : "+l"(acc) : "l"(u), "l"(y));
}
__device__ __forceinline__ unsigned long long dup2(float y) {
    unsigned long long r;
    asm("mov.b64 %0, {%1, %1};" : "=l"(r) : "f"(y));
    return r;
}
__device__ __forceinline__ float2 unpk2(unsigned long long v) {
    float2 r;
    asm("mov.b64 {%0, %1}, %2;" : "=f"(r.x), "=f"(r.y) : "l"(v));
    return r;
}

// SMEM layout (floats):
//   [0,     13760)  coeff table (55 KB)
//   [13760, 54720)  xS: x[40][256 threads][4 b]  (160 KB)
//                   reused after phases: basis[16][64][20] (80 KB) + Wlin (48 KB)
#define SMEM_FLOATS 54720
#define SMEM_BYTES  (SMEM_FLOATS * 4)
#define BSTRIDE 20     // basis row stride in floats

__global__ __launch_bounds__(NT, 1)
void main_kernel(const float* __restrict__ f0,  const float* __restrict__ f1,
                 const float* __restrict__ f2,  const float* __restrict__ f3,
                 const float* __restrict__ attrs,
                 const float* __restrict__ W1_0, const float* __restrict__ W2_0,
                 const float* __restrict__ Wl0,  const float* __restrict__ sc0,
                 const float* __restrict__ W1_1, const float* __restrict__ W2_1,
                 const float* __restrict__ Wl1,  const float* __restrict__ sc1,
                 const float* __restrict__ W1_2, const float* __restrict__ W2_2,
                 const float* __restrict__ Wl2,  const float* __restrict__ sc2,
                 float* __restrict__ out, int B) {
    extern __shared__ float S[];
    float* tabS = S;            // 13760 floats
    float* xS   = S + 13760;    // 40960 floats

    const int tid = threadIdx.x;
    const int g   = tid >> 6;        // b-group 0..3
    const int c   = tid & 63;        // channel
    const int b0  = blockIdx.x * NB + g * NBSUB;

    // cooperative copy of the packed table into smem
    {
        const float4* gt4 = (const float4*)g_table;
        float4* tp4 = (float4*)tabS;
#pragma unroll
        for (int k = 0; k < 14; k++) {
            int idx = k * NT + tid;
            if (idx < NROWS * TS / 4) tp4[idx] = gt4[idx];
        }
    }

    // gather x for 4 b's: xS[i*1024 + tid*4 + s]
#pragma unroll
    for (int s = 0; s < NBSUB; s++) {
        int bb = b0 + s; if (bb >= B) bb = B - 1;
        const int base = bb * 64 + c;
        xS[tid * 4 + s] = f0[base];
#pragma unroll
        for (int k = 0; k < 3; k++)
            xS[(1 + k) * 1024 + tid * 4 + s]  = f1[base * 3 + k];
#pragma unroll
        for (int k = 0; k < 9; k++)
            xS[(4 + k) * 1024 + tid * 4 + s]  = f2[base * 9 + k];
#pragma unroll
        for (int k = 0; k < 27; k++)
            xS[(13 + k) * 1024 + tid * 4 + s] = f3[base * 27 + k];
    }

    // element-aware channel weights for the 4 b's
    float w1v[NBSUB][3], w2v[NBSUB][3];
#pragma unroll
    for (int s = 0; s < NBSUB; s++) {
        int bb = b0 + s; if (bb >= B) bb = B - 1;
        float a10 = 0.f, a11 = 0.f, a12 = 0.f, a20 = 0.f, a21 = 0.f, a22 = 0.f;
#pragma unroll
        for (int e = 0; e < 10; e++) {
            float a = __ldg(&attrs[bb * 10 + e]);
            a10 += a * __ldg(&W1_0[e * 64 + c]);
            a20 += a * __ldg(&W2_0[e * 64 + c]);
            a11 += a * __ldg(&W1_1[e * 64 + c]);
            a21 += a * __ldg(&W2_1[e * 64 + c]);
            a12 += a * __ldg(&W1_2[e * 64 + c]);
            a22 += a * __ldg(&W2_2[e * 64 + c]);
        }
        w1v[s][0] = a10; w1v[s][1] = a11; w1v[s][2] = a12;
        w2v[s][0] = a20; w2v[s][1] = a21; w2v[s][2] = a22;
    }
    __syncthreads();

    // ---- phase A: a2[s][m] = sum_{i<=j} u[p][m] * x_i[s] * x_j[s] ----
    unsigned long long a2[NBSUB][7];
#pragma unroll
    for (int s = 0; s < NBSUB; s++)
#pragma unroll
        for (int k = 0; k < 7; k++) a2[s][k] = 0ull;

    const ulonglong2* trow = (const ulonglong2*)tabS;
    const char* xtb = (const char*)xS + tid * 16;

    for (int i = 0; i < DIM; i++) {
        const float4 xi = *(const float4*)(xtb + i * XROWB);
        const char* xjp = xtb + i * XROWB;
#pragma unroll 2
        for (int j = i; j < DIM; j++) {
            ulonglong2 q0 = trow[0];
            ulonglong2 q1 = trow[1];
            ulonglong2 q2 = trow[2];
            ulonglong2 q3 = trow[3];
            trow += 4;
            float4 xj = *(const float4*)xjp;
            xjp += XROWB;
            unsigned long long y0 = dup2(xi.x * xj.x);
            unsigned long long y1 = dup2(xi.y * xj.y);
            unsigned long long y2 = dup2(xi.z * xj.z);
            unsigned long long y3 = dup2(xi.w * xj.w);
            fma2(a2[0][0], q0.x, y0); fma2(a2[1][0], q0.x, y1);
            fma2(a2[2][0], q0.x, y2); fma2(a2[3][0], q0.x, y3);
            fma2(a2[0][1], q0.y, y0); fma2(a2[1][1], q0.y, y1);
            fma2(a2[2][1], q0.y, y2); fma2(a2[3][1], q0.y, y3);
            fma2(a2[0][2], q1.x, y0); fma2(a2[1][2], q1.x, y1);
            fma2(a2[2][2], q1.x, y2); fma2(a2[3][2], q1.x, y3);
            fma2(a2[0][3], q1.y, y0); fma2(a2[1][3], q1.y, y1);
            fma2(a2[2][3], q1.y, y2); fma2(a2[3][3], q1.y, y3);
            fma2(a2[0][4], q2.x, y0); fma2(a2[1][4], q2.x, y1);
            fma2(a2[2][4], q2.x, y2); fma2(a2[3][4], q2.x, y3);
            fma2(a2[0][5], q2.y, y0); fma2(a2[1][5], q2.y, y1);
            fma2(a2[2][5], q2.y, y2); fma2(a2[3][5], q2.y, y3);
            fma2(a2[0][6], q3.x, y0); fma2(a2[1][6], q3.x, y1);
            fma2(a2[2][6], q3.x, y2); fma2(a2[3][6], q3.x, y3);
        }
    }

    // ---- phase B: a1[s][m] = U1[m,:] . x[s] ----
    unsigned long long a1[NBSUB][7];
#pragma unroll
    for (int s = 0; s < NBSUB; s++)
#pragma unroll
        for (int k = 0; k < 7; k++) a1[s][k] = 0ull;

#pragma unroll 2
    for (int i = 0; i < DIM; i++, trow += 4) {
        ulonglong2 q0 = trow[0];
        ulonglong2 q1 = trow[1];
        ulonglong2 q2 = trow[2];
        ulonglong2 q3 = trow[3];
        float4 xi = *(const float4*)(xtb + i * XROWB);
        unsigned long long y0 = dup2(xi.x);
        unsigned long long y1 = dup2(xi.y);
        unsigned long long y2 = dup2(xi.z);
        unsigned long long y3 = dup2(xi.w);
        fma2(a1[0][0], q0.x, y0); fma2(a1[1][0], q0.x, y1);
        fma2(a1[2][0], q0.x, y2); fma2(a1[3][0], q0.x, y3);
        fma2(a1[0][1], q0.y, y0); fma2(a1[1][1], q0.y, y1);
        fma2(a1[2][1], q0.y, y2); fma2(a1[3][1], q0.y, y3);
        fma2(a1[0][2], q1.x, y0); fma2(a1[1][2], q1.x, y1);
        fma2(a1[2][2], q1.x, y2); fma2(a1[3][2], q1.x, y3);
        fma2(a1[0][3], q1.y, y0); fma2(a1[1][3], q1.y, y1);
        fma2(a1[2][3], q1.y, y2); fma2(a1[3][3], q1.y, y3);
        fma2(a1[0][4], q2.x, y0); fma2(a1[1][4], q2.x, y1);
        fma2(a1[2][4], q2.x, y2); fma2(a1[3][4], q2.x, y3);
        fma2(a1[0][5], q2.y, y0); fma2(a1[1][5], q2.y, y1);
        fma2(a1[2][5], q2.y, y2); fma2(a1[3][5], q2.y, y3);
        fma2(a1[0][6], q3.x, y0); fma2(a1[1][6], q3.x, y1);
        fma2(a1[2][6], q3.x, y2); fma2(a1[3][6], q3.x, y3);
    }

    __syncthreads();   // everyone done reading xS before we overwrite it

    // reuse xS region: basis[16 b][64 c][20] + Wlin cache
    float* basS = xS;                       // 20480 floats
    float* wlS  = xS + 20480;               // 12288 floats

    const int LSEL[14] = {0, 1, 1, 1, 2, 2, 2, 2, 2, 2, 2, 2, 2, 0};
#pragma unroll
    for (int s = 0; s < NBSUB; s++) {
        float* bs = basS + ((g * NBSUB + s) * 64 + c) * BSTRIDE;
#pragma unroll
        for (int k = 0; k < 7; k++) {
            float2 v2 = unpk2(a2[s][k]);
            float2 v1 = unpk2(a1[s][k]);
            int m0 = 2 * k, m1 = 2 * k + 1;
            bs[m0] = v1.x * w1v[s][LSEL[m0]] + v2.x * w2v[s][LSEL[m0]];
            if (m1 < 13)
                bs[m1] = v1.y * w1v[s][LSEL[m1]] + v2.y * w2v[s][LSEL[m1]];
        }
    }

    // Wlin cache: wlS[l*4096 + cc*64 + o]
    {
        const float4* a0p = (const float4*)Wl0;
        const float4* a1p = (const float4*)Wl1;
        const float4* a2p = (const float4*)Wl2;
        float4* w4 = (float4*)wlS;
#pragma unroll
        for (int k = 0; k < 4; k++) {
            int idx = k * NT + tid;
            w4[idx]        = a0p[idx];
            w4[1024 + idx] = a1p[idx];
            w4[2048 + idx] = a2p[idx];
        }
    }
    __syncthreads();

    // ---- self-interaction: r[s][m] = sum_cc basis[b_s][cc][m] * Wlin_l[cc][c] ----
    float r[NBSUB][13];
#pragma unroll
    for (int s = 0; s < NBSUB; s++)
#pragma unroll
        for (int m = 0; m < 13; m++) r[s][m] = 0.0f;

#pragma unroll 2
    for (int cc = 0; cc < 64; cc++) {
        float wv0 = wlS[cc * 64 + c];
        float wv1 = wlS[4096 + cc * 64 + c];
        float wv2 = wlS[8192 + cc * 64 + c];
#pragma unroll
        for (int s = 0; s < NBSUB; s++) {
            const float* br = basS + ((g * NBSUB + s) * 64 + cc) * BSTRIDE;
            float4 q0 = *(const float4*)(br);
            float4 q1 = *(const float4*)(br + 4);
            float4 q2 = *(const float4*)(br + 8);
            float b12 = br[12];
            r[s][0]  += q0.x * wv0;
            r[s][1]  += q0.y * wv1;
            r[s][2]  += q0.z * wv1;
            r[s][3]  += q0.w * wv1;
            r[s][4]  += q1.x * wv2;
            r[s][5]  += q1.y * wv2;
            r[s][6]  += q1.z * wv2;
            r[s][7]  += q1.w * wv2;
            r[s][8]  += q2.x * wv2;
            r[s][9]  += q2.y * wv2;
            r[s][10] += q2.z * wv2;
            r[s][11] += q2.w * wv2;
            r[s][12] += b12  * wv2;
        }
    }

    // ---- outputs: concat [out0 (B,C)] [out1 (B,C,3)] [out2 (B,C,9)] ----
    float* o0 = out;
    float* o1 = out + (size_t)B * 64;
    float* o2 = out + (size_t)B * 64 * 4;
#pragma unroll
    for (int s = 0; s < NBSUB; s++) {
        int bb = b0 + s;
        if (bb >= B) break;
        const int bo = bb * 64 + c;
        o0[bo] = r[s][0] + __ldg(&sc0[bo]);
#pragma unroll
        for (int k = 0; k < 3; k++)
            o1[bo * 3 + k] = r[s][1 + k] + __ldg(&sc1[bo * 3 + k]);
#pragma unroll
        for (int k = 0; k < 9; k++)
            o2[bo * 9 + k] = r[s][4 + k] + __ldg(&sc2[bo * 9 + k]);
    }
}

extern "C" void kernel_launch(void* const* d_in, const int* in_sizes, int n_in,
                              void* d_out, int out_size) {
    const float* f0    = (const float*)d_in[0];
    const float* f1    = (const float*)d_in[1];
    const float* f2    = (const float*)d_in[2];
    const float* f3    = (const float*)d_in[3];
    const float* attrs = (const float*)d_in[4];
    const float* U2_0  = (const float*)d_in[5];
    const float* U1_0  = (const float*)d_in[6];
    const float* W1_0  = (const float*)d_in[7];
    const float* W2_0  = (const float*)d_in[8];
    const float* Wl0   = (const float*)d_in[9];
    const float* sc0   = (const float*)d_in[10];
    const float* U2_1  = (const float*)d_in[11];
    const float* U1_1  = (const float*)d_in[12];
    const float* W1_1  = (const float*)d_in[13];
    const float* W2_1  = (const float*)d_in[14];
    const float* Wl1   = (const float*)d_in[15];
    const float* sc1   = (const float*)d_in[16];
    const float* U2_2  = (const float*)d_in[17];
    const float* U1_2  = (const float*)d_in[18];
    const float* W1_2  = (const float*)d_in[19];
    const float* W2_2  = (const float*)d_in[20];
    const float* Wl2   = (const float*)d_in[21];
    const float* sc2   = (const float*)d_in[22];

    const int B = in_sizes[0] / 64;

    cudaFuncSetAttribute(main_kernel,
                         cudaFuncAttributeMaxDynamicSharedMemorySize, SMEM_BYTES);

    prep_kernel<<<(NROWS + 255) / 256, 256>>>(U2_0, U1_0, U2_1, U1_1, U2_2, U1_2);

    const int grid = (B + NB - 1) / NB;
    main_kernel<<<grid, NT, SMEM_BYTES>>>(f0, f1, f2, f3, attrs,
                                          W1_0, W2_0, Wl0, sc0,
                                          W1_1, W2_1, Wl1, sc1,
                                          W1_2, W2_2, Wl2, sc2,
                                          (float*)d_out, B);
}